// round 15
// baseline (speedup 1.0000x reference)
#include <cuda_runtime.h>
#include <math.h>
#include <stdint.h>

#define NTOK 65536
#define ADIM 32
typedef unsigned long long ull;

__device__ float g_bufA[(size_t)NTOK * 512];
__device__ float g_bufB[(size_t)NTOK * 1024];
__device__ float g_ze [(size_t)NTOK * 256];
__device__ float g_w1t[1024 * 512];
__device__ float g_w2t[256 * 1024];
__device__ float g_cbn[1024 * 256];
__device__ float g_cbsq[1024];
__device__ float g_dt0[1024 * 1024];
__device__ float g_dt1[1024 * 512];
__device__ float g_dt2[1024 * 32];
__device__ double g_acc[2];

// ---- helpers ----
__device__ __forceinline__ ull f2pack(float lo, float hi) {
    ull r; asm("mov.b64 %0, {%1, %2};" : "=l"(r) : "f"(lo), "f"(hi)); return r;
}
__device__ __forceinline__ void f2unpack(ull p, float& lo, float& hi) {
    asm("mov.b64 {%0, %1}, %2;" : "=f"(lo), "=f"(hi) : "l"(p));
}
__device__ __forceinline__ void fma2(ull& d, ull a, ull b) {
    asm("fma.rn.f32x2 %0, %1, %2, %0;" : "+l"(d) : "l"(a), "l"(b));
}
__device__ __forceinline__ float tf32_rn(float x) {
    unsigned u; asm("cvt.rna.tf32.f32 %0, %1;" : "=r"(u) : "f"(x));
    return __uint_as_float(u);
}
__device__ __forceinline__ float gelu_t(float x) {
    float u = 0.7978845608028654f * (x + 0.044715f * x * x * x);
    return 0.5f * x * (1.0f + tanhf(u));
}
__device__ __forceinline__ void mma8(float* c, const uint32_t* a, const uint32_t* b) {
    asm volatile(
        "mma.sync.aligned.m16n8k8.row.col.f32.tf32.tf32.f32 "
        "{%0,%1,%2,%3}, {%4,%5,%6,%7}, {%8,%9}, {%0,%1,%2,%3};"
        : "+f"(c[0]), "+f"(c[1]), "+f"(c[2]), "+f"(c[3])
        : "r"(a[0]), "r"(a[1]), "r"(a[2]), "r"(a[3]), "r"(b[0]), "r"(b[1]));
}
__device__ __forceinline__ void ldm4(uint32_t* d, uint32_t a) {
    asm volatile("ldmatrix.sync.aligned.m8n8.x4.shared.b16 {%0,%1,%2,%3}, [%4];"
        : "=r"(d[0]), "=r"(d[1]), "=r"(d[2]), "=r"(d[3]) : "r"(a));
}
__device__ __forceinline__ uint32_t smem_addr(const void* p) {
    uint32_t a;
    asm("{ .reg .u64 t; cvta.to.shared.u64 t, %1; cvt.u32.u64 %0, t; }" : "=r"(a) : "l"(p));
    return a;
}
__device__ __forceinline__ void split4(float4 v, float4& h, float4& l) {
    h.x = tf32_rn(v.x); l.x = tf32_rn(v.x - h.x);
    h.y = tf32_rn(v.y); l.y = tf32_rn(v.y - h.y);
    h.z = tf32_rn(v.z); l.z = tf32_rn(v.z - h.z);
    h.w = tf32_rn(v.w); l.w = tf32_rn(v.w - h.w);
}

#define KP 36  // padded smem pitch (floats); ldmatrix row-starts conflict-free

// 4 k8-steps of 3-split mma over one 32-wide K tile (warp tile 64x32), ldmatrix loads
__device__ __forceinline__ void mma_ktile(const float (*Ah)[KP], const float (*Al)[KP],
                                          const float (*Bh)[KP], const float (*Bl)[KP],
                                          int wm, int wn, int lane, float acc[4][4][4]) {
    const int j8 = lane & 7;
    const int arow = wm * 64 + ((lane >> 3) & 1) * 8 + j8;
    const int acol = (lane >> 4) << 2;
    const int brow = wn * 32 + ((lane >> 4) << 3) + j8;
    const int bcol = ((lane >> 3) & 1) << 2;
    const uint32_t aAh = smem_addr(&Ah[arow][acol]);
    const uint32_t aAl = smem_addr(&Al[arow][acol]);
    const uint32_t aBh = smem_addr(&Bh[brow][bcol]);
    const uint32_t aBl = smem_addr(&Bl[brow][bcol]);
    const uint32_t MT = 16 * KP * 4;
#pragma unroll
    for (int ks = 0; ks < 4; ks++) {
        const uint32_t ko = ks * 32;
        uint32_t ah[4][4], bh[2][4], bl[2][4];
#pragma unroll
        for (int mt = 0; mt < 4; mt++) ldm4(ah[mt], aAh + mt * MT + ko);
#pragma unroll
        for (int p = 0; p < 2; p++) {
            ldm4(bh[p], aBh + p * MT + ko);
            ldm4(bl[p], aBl + p * MT + ko);
        }
#pragma unroll
        for (int mt = 0; mt < 4; mt++)
#pragma unroll
            for (int nt = 0; nt < 4; nt++) {
                mma8(acc[mt][nt], ah[mt], &bh[nt >> 1][(nt & 1) * 2]);
                mma8(acc[mt][nt], ah[mt], &bl[nt >> 1][(nt & 1) * 2]);
            }
        uint32_t al_[4][4];
#pragma unroll
        for (int mt = 0; mt < 4; mt++) ldm4(al_[mt], aAl + mt * MT + ko);
#pragma unroll
        for (int mt = 0; mt < 4; mt++)
#pragma unroll
            for (int nt = 0; nt < 4; nt++)
                mma8(acc[mt][nt], al_[mt], &bh[nt >> 1][(nt & 1) * 2]);
    }
}

// ---- tensor-op 3-split TF32 GEMM: C = act(A[M,K] @ B[N,K]^T + bias) ----
// A prefetched into registers (16 regs, DRAM-latency operand); B loaded in the
// load phase (L2-hot weights). Both split to tf32 hi/lo at STS time.
template<bool GELU>
__global__ __launch_bounds__(256, 2)
void tmma(const float* __restrict__ A, const float* __restrict__ B,
          const float* __restrict__ bias, float* __restrict__ C, int N, int K) {
    extern __shared__ float sm[];
    float (*Ah)[KP] = (float(*)[KP])sm;
    float (*Al)[KP] = (float(*)[KP])(sm + 128 * KP);
    float (*Bh)[KP] = (float(*)[KP])(sm + 2 * 128 * KP);
    float (*Bl)[KP] = (float(*)[KP])(sm + 3 * 128 * KP);
    const int tid = threadIdx.x, wid = tid >> 5, lane = tid & 31;
    const int g = lane >> 2, t = lane & 3;
    const int wm = wid & 1, wn = wid >> 1;
    const size_t m0 = (size_t)blockIdx.y * 128;
    const int n0 = blockIdx.x * 128;
    const int r_ = tid >> 3, c4_ = (tid & 7) << 2;   // rows r_+32i, fixed col group

    float acc[4][4][4] = {};
    float4 pa[4];
    const int T = K >> 5;
#pragma unroll
    for (int i = 0; i < 4; i++)
        pa[i] = *(const float4*)(A + (m0 + r_ + 32 * i) * (size_t)K + c4_);

    for (int kt = 0; kt < T; kt++) {
        const int kg = kt << 5;
        __syncthreads();
#pragma unroll
        for (int i = 0; i < 4; i++) {
            float4 h, l;
            split4(pa[i], h, l);
            *(float4*)&Ah[r_ + 32 * i][c4_] = h; *(float4*)&Al[r_ + 32 * i][c4_] = l;
            float4 vb = *(const float4*)(B + ((size_t)n0 + r_ + 32 * i) * (size_t)K + kg + c4_);
            split4(vb, h, l);
            *(float4*)&Bh[r_ + 32 * i][c4_] = h; *(float4*)&Bl[r_ + 32 * i][c4_] = l;
        }
        __syncthreads();
        if (kt + 1 < T) {
            const int kn = (kt + 1) << 5;
#pragma unroll
            for (int i = 0; i < 4; i++)
                pa[i] = *(const float4*)(A + (m0 + r_ + 32 * i) * (size_t)K + kn + c4_);
        }
        mma_ktile(Ah, Al, Bh, Bl, wm, wn, lane, acc);
    }

#pragma unroll
    for (int mt = 0; mt < 4; mt++) {
#pragma unroll
        for (int nt = 0; nt < 4; nt++) {
            int col = n0 + wn * 32 + nt * 8 + 2 * t;
            float b0 = bias[col], b1 = bias[col + 1];
            size_t r0 = (m0 + wm * 64 + mt * 16 + g) * (size_t)N + col;
            size_t r1 = r0 + 8 * (size_t)N;
            float x0 = acc[mt][nt][0] + b0, x1 = acc[mt][nt][1] + b1;
            float x2 = acc[mt][nt][2] + b0, x3 = acc[mt][nt][3] + b1;
            if (GELU) { x0 = gelu_t(x0); x1 = gelu_t(x1); x2 = gelu_t(x2); x3 = gelu_t(x3); }
            *(float2*)(C + r0) = make_float2(x0, x1);
            *(float2*)(C + r1) = make_float2(x2, x3);
        }
    }
}

// ---- tensor-op VQ: dist GEMM + argmin + vq loss + recon gather/loss ----
// ZE (A operand) register-prefetched across the ct x kt loop nest; codebook (B)
// loaded in the load phase (L2-hot).
__global__ __launch_bounds__(256, 2)
void vq_t(const float* __restrict__ ZE, const float* __restrict__ tab,
          const float* __restrict__ action, const float* __restrict__ dimw,
          float* __restrict__ outAH, float* __restrict__ outIdxF) {
    extern __shared__ float sm[];
    float (*Ah)[KP] = (float(*)[KP])sm;
    float (*Al)[KP] = (float(*)[KP])(sm + 128 * KP);
    float (*Bh)[KP] = (float(*)[KP])(sm + 2 * 128 * KP);
    float (*Bl)[KP] = (float(*)[KP])(sm + 3 * 128 * KP);
    __shared__ float scb[1024];
    __shared__ ull bestp[128];
    __shared__ float salpha[128], snorm[128], sdimw[32];
    __shared__ double dred[8], rred[8];
    const int tid = threadIdx.x, wid = tid >> 5, lane = tid & 31;
    const int g = lane >> 2, t = lane & 3;
    const int wm = wid & 1, wn = wid >> 1;
    const size_t m0 = (size_t)blockIdx.x * 128;
    const int r_ = tid >> 3, c4_ = (tid & 7) << 2;

    for (int e = tid; e < 1024; e += 256) scb[e] = g_cbsq[e];
    if (tid < 32) sdimw[tid] = dimw[tid];
    if (tid < 128) bestp[tid] = ~0ull;
    {
        const int row = tid >> 1, half = tid & 1;
        const float* rp = ZE + (m0 + row) * 256 + half * 128;
        float s = 0.f;
#pragma unroll
        for (int i = 0; i < 32; i++) {
            float4 v = *(const float4*)(rp + i * 4);
            s += v.x * v.x + v.y * v.y + v.z * v.z + v.w * v.w;
        }
        s += __shfl_xor_sync(0xffffffffu, s, 1);
        if (half == 0) { snorm[row] = s; salpha[row] = 1.0f / (sqrtf(s) + 1e-8f); }
    }
    __syncthreads();

    float4 pa[4];
#pragma unroll
    for (int i = 0; i < 4; i++)
        pa[i] = *(const float4*)(ZE + (m0 + r_ + 32 * i) * 256 + c4_);

    for (int ct = 0; ct < 8; ct++) {
        const int cbase = ct * 128;
        float acc[4][4][4] = {};
        for (int kt = 0; kt < 8; kt++) {
            const int kg = kt << 5;
            __syncthreads();
#pragma unroll
            for (int i = 0; i < 4; i++) {
                float4 h, l;
                split4(pa[i], h, l);
                *(float4*)&Ah[r_ + 32 * i][c4_] = h; *(float4*)&Al[r_ + 32 * i][c4_] = l;
                float4 vb = *(const float4*)(g_cbn + ((size_t)cbase + r_ + 32 * i) * 256 + kg + c4_);
                split4(vb, h, l);
                *(float4*)&Bh[r_ + 32 * i][c4_] = h; *(float4*)&Bl[r_ + 32 * i][c4_] = l;
            }
            __syncthreads();
            {   // prefetch next ZE tile (wraps to k=0 for the next ct)
                const int kn = (kt + 1 < 8) ? ((kt + 1) << 5) : 0;
                if (kt + 1 < 8 || ct + 1 < 8) {
#pragma unroll
                    for (int i = 0; i < 4; i++)
                        pa[i] = *(const float4*)(ZE + (m0 + r_ + 32 * i) * 256 + kn + c4_);
                }
            }
            mma_ktile(Ah, Al, Bh, Bl, wm, wn, lane, acc);
        }
#pragma unroll
        for (int mt = 0; mt < 4; mt++) {
            const int r0 = wm * 64 + mt * 16 + g, r1 = r0 + 8;
            const float m2a0 = -2.0f * salpha[r0], m2a1 = -2.0f * salpha[r1];
            ull p0 = ~0ull, p1 = ~0ull;
#pragma unroll
            for (int nt = 0; nt < 4; nt++) {
                int c = cbase + wn * 32 + nt * 8 + 2 * t;
                float s0 = scb[c], s1 = scb[c + 1];
                float v00 = fmaf(m2a0, acc[mt][nt][0], s0);
                float v01 = fmaf(m2a0, acc[mt][nt][1], s1);
                float v10 = fmaf(m2a1, acc[mt][nt][2], s0);
                float v11 = fmaf(m2a1, acc[mt][nt][3], s1);
                p0 = min(p0, ((ull)__float_as_uint(v00 + 8.f) << 32) | (unsigned)c);
                p0 = min(p0, ((ull)__float_as_uint(v01 + 8.f) << 32) | (unsigned)(c + 1));
                p1 = min(p1, ((ull)__float_as_uint(v10 + 8.f) << 32) | (unsigned)c);
                p1 = min(p1, ((ull)__float_as_uint(v11 + 8.f) << 32) | (unsigned)(c + 1));
            }
#pragma unroll
            for (int off = 1; off < 4; off <<= 1) {
                p0 = min(p0, __shfl_xor_sync(0xffffffffu, p0, off));
                p1 = min(p1, __shfl_xor_sync(0xffffffffu, p1, off));
            }
            if (t == 0) { atomicMin(&bestp[r0], p0); atomicMin(&bestp[r1], p1); }
        }
        __syncthreads();
    }

    double lsum = 0.0;
    if (tid < 128) {
        ull bp = bestp[tid];
        int besti = (int)(unsigned)(bp & 0xffffffffu);
        outIdxF[blockIdx.x * 128 + tid] = (float)besti;
        float bd = __uint_as_float((unsigned)(bp >> 32)) - 8.0f;
        float a = salpha[tid];
        lsum = (double)(a * a * snorm[tid] + bd);
    }
#pragma unroll
    for (int o = 16; o; o >>= 1) lsum += __shfl_xor_sync(0xffffffffu, lsum, o);
    if ((tid & 31) == 0) dred[tid >> 5] = lsum;

    double rsum = 0.0;
    for (int rr = wid; rr < 128; rr += 8) {
        int idx = (int)(unsigned)(bestp[rr] & 0xffffffffu);
        float ah = tab[(size_t)idx * 32 + lane];
        size_t gi = (m0 + rr) * 32 + lane;
        outAH[gi] = ah;
        float d = action[gi] - ah;
        rsum += (double)(d * d * sdimw[lane]);
    }
#pragma unroll
    for (int o = 16; o; o >>= 1) rsum += __shfl_xor_sync(0xffffffffu, rsum, o);
    if (lane == 0) rred[wid] = rsum;
    __syncthreads();
    if (tid == 0) {
        double tt = 0.0, r = 0.0;
        for (int i = 0; i < 8; i++) { tt += dred[i]; r += rred[i]; }
        atomicAdd(&g_acc[1], tt);
        atomicAdd(&g_acc[0], r);
    }
}

// ---- fp32 FFMA GEMM for e0 ----
#define SPAD 132
__global__ __launch_bounds__(256, 2)
void sgemm_e0(const float* __restrict__ A, const float* __restrict__ B,
              const float* __restrict__ bias, float* __restrict__ C, int M, int N, int K) {
    __shared__ float As[2][16][SPAD];
    __shared__ float Bs[2][16][SPAD];
    const int tid = threadIdx.x;
    const int tx = tid & 15, ty = tid >> 4;
    const int aRow = tid >> 2, aCol4 = (tid & 3) << 2;
    const int bRow = tid >> 5, bCol4 = (tid & 31) << 2;
    const float* Ab = A + (size_t)blockIdx.y * 128 * K;
    const float* Bb = B + (size_t)blockIdx.x * 128;
    ull acc[8][4];
#pragma unroll
    for (int i = 0; i < 8; i++)
#pragma unroll
        for (int j = 0; j < 4; j++) acc[i][j] = 0ull;
    const int T = K >> 4;
    float4 pa0, pa1, pb0, pb1;
    pa0 = *(const float4*)(Ab + (size_t)aRow * K + aCol4);
    pa1 = *(const float4*)(Ab + (size_t)(aRow + 64) * K + aCol4);
    pb0 = *(const float4*)(Bb + (size_t)bRow * N + bCol4);
    pb1 = *(const float4*)(Bb + (size_t)(bRow + 8) * N + bCol4);
    {
        float* a0p = &As[0][aCol4][aRow];
        a0p[0] = pa0.x; a0p[SPAD] = pa0.y; a0p[2 * SPAD] = pa0.z; a0p[3 * SPAD] = pa0.w;
        float* a1p = &As[0][aCol4][aRow + 64];
        a1p[0] = pa1.x; a1p[SPAD] = pa1.y; a1p[2 * SPAD] = pa1.z; a1p[3 * SPAD] = pa1.w;
        *(float4*)(&Bs[0][bRow][bCol4]) = pb0;
        *(float4*)(&Bs[0][bRow + 8][bCol4]) = pb1;
    }
    __syncthreads();
    for (int tt = 0; tt < T; tt++) {
        const int cur = tt & 1;
        if (tt + 1 < T) {
            const int k0 = (tt + 1) << 4;
            pa0 = *(const float4*)(Ab + (size_t)aRow * K + k0 + aCol4);
            pa1 = *(const float4*)(Ab + (size_t)(aRow + 64) * K + k0 + aCol4);
            pb0 = *(const float4*)(Bb + (size_t)(k0 + bRow) * N + bCol4);
            pb1 = *(const float4*)(Bb + (size_t)(k0 + bRow + 8) * N + bCol4);
        }
#pragma unroll
        for (int k = 0; k < 16; k++) {
            float4 a0 = *(const float4*)(&As[cur][k][ty * 4]);
            float4 a1 = *(const float4*)(&As[cur][k][ty * 4 + 64]);
            ulonglong2 b01 = *(const ulonglong2*)(&Bs[cur][k][tx * 4]);
            ulonglong2 b23 = *(const ulonglong2*)(&Bs[cur][k][tx * 4 + 64]);
            ull bb2[4] = {b01.x, b01.y, b23.x, b23.y};
            float af[8] = {a0.x, a0.y, a0.z, a0.w, a1.x, a1.y, a1.z, a1.w};
#pragma unroll
            for (int i = 0; i < 8; i++) {
                ull a2 = f2pack(af[i], af[i]);
#pragma unroll
                for (int jp = 0; jp < 4; jp++) fma2(acc[i][jp], a2, bb2[jp]);
            }
        }
        if (tt + 1 < T) {
            const int nxt = cur ^ 1;
            float* a0p = &As[nxt][aCol4][aRow];
            a0p[0] = pa0.x; a0p[SPAD] = pa0.y; a0p[2 * SPAD] = pa0.z; a0p[3 * SPAD] = pa0.w;
            float* a1p = &As[nxt][aCol4][aRow + 64];
            a1p[0] = pa1.x; a1p[SPAD] = pa1.y; a1p[2 * SPAD] = pa1.z; a1p[3 * SPAD] = pa1.w;
            *(float4*)(&Bs[nxt][bRow][bCol4]) = pb0;
            *(float4*)(&Bs[nxt][bRow + 8][bCol4]) = pb1;
        }
        __syncthreads();
    }
    const int row0 = blockIdx.y * 128;
    const int c0g = blockIdx.x * 128 + tx * 4;
    float bl[4], bh[4];
#pragma unroll
    for (int j = 0; j < 4; j++) { bl[j] = bias[c0g + j]; bh[j] = bias[c0g + 64 + j]; }
#pragma unroll
    for (int i = 0; i < 8; i++) {
        const int row = row0 + ((i < 4) ? (ty * 4 + i) : (64 + ty * 4 + i - 4));
        float c[8];
#pragma unroll
        for (int jp = 0; jp < 4; jp++) f2unpack(acc[i][jp], c[jp * 2], c[jp * 2 + 1]);
#pragma unroll
        for (int j = 0; j < 4; j++) {
            c[j] = gelu_t(c[j] + bl[j]);
            c[4 + j] = gelu_t(c[4 + j] + bh[j]);
        }
        float* Cp = C + (size_t)row * N + c0g;
        *(float4*)(Cp) = make_float4(c[0], c[1], c[2], c[3]);
        *(float4*)(Cp + 64) = make_float4(c[4], c[5], c[6], c[7]);
    }
}

// ---- small fp32 GEMM for decoder table ----
template<bool GELU>
__global__ __launch_bounds__(128)
void sgemm64(const float* __restrict__ A, const float* __restrict__ B,
             const float* __restrict__ bias, float* __restrict__ C, int M, int N, int K) {
    __shared__ float As[16][68];
    __shared__ float Bs[16][68];
    const int tid = threadIdx.x;
    const int tx = tid & 7, ty = tid >> 3;
    const int aRow = tid >> 1, aCol8 = (tid & 1) * 8;
    const int bRow = tid >> 3, bCol8 = (tid & 7) * 8;
    const float* Ab = A + (size_t)blockIdx.y * 64 * K;
    const float* Bb = B + (size_t)blockIdx.x * 64;
    ull acc[4][4];
#pragma unroll
    for (int i = 0; i < 4; i++)
#pragma unroll
        for (int j = 0; j < 4; j++) acc[i][j] = 0ull;
    for (int k0 = 0; k0 < K; k0 += 16) {
        float4 va0 = *(const float4*)(Ab + (size_t)aRow * K + k0 + aCol8);
        float4 va1 = *(const float4*)(Ab + (size_t)aRow * K + k0 + aCol8 + 4);
        float4 vb0 = *(const float4*)(Bb + (size_t)(k0 + bRow) * N + bCol8);
        float4 vb1 = *(const float4*)(Bb + (size_t)(k0 + bRow) * N + bCol8 + 4);
        __syncthreads();
        As[aCol8 + 0][aRow] = va0.x; As[aCol8 + 1][aRow] = va0.y;
        As[aCol8 + 2][aRow] = va0.z; As[aCol8 + 3][aRow] = va0.w;
        As[aCol8 + 4][aRow] = va1.x; As[aCol8 + 5][aRow] = va1.y;
        As[aCol8 + 6][aRow] = va1.z; As[aCol8 + 7][aRow] = va1.w;
        *(float4*)(&Bs[bRow][bCol8]) = vb0;
        *(float4*)(&Bs[bRow][bCol8 + 4]) = vb1;
        __syncthreads();
#pragma unroll
        for (int k = 0; k < 16; k++) {
            float4 a = *(const float4*)(&As[k][ty * 4]);
            ulonglong2 b01 = *(const ulonglong2*)(&Bs[k][tx * 4]);
            ulonglong2 b23 = *(const ulonglong2*)(&Bs[k][tx * 4 + 32]);
            ull bb2[4] = {b01.x, b01.y, b23.x, b23.y};
            float af[4] = {a.x, a.y, a.z, a.w};
#pragma unroll
            for (int i = 0; i < 4; i++) {
                ull a2 = f2pack(af[i], af[i]);
#pragma unroll
                for (int jp = 0; jp < 4; jp++) fma2(acc[i][jp], a2, bb2[jp]);
            }
        }
    }
    const int row0 = blockIdx.y * 64 + ty * 4;
    const int col0 = blockIdx.x * 64 + tx * 4;
    float bl[4], bh[4];
#pragma unroll
    for (int j = 0; j < 4; j++) { bl[j] = bias[col0 + j]; bh[j] = bias[col0 + 32 + j]; }
#pragma unroll
    for (int i = 0; i < 4; i++) {
        float c[8];
#pragma unroll
        for (int jp = 0; jp < 4; jp++) f2unpack(acc[i][jp], c[jp * 2], c[jp * 2 + 1]);
#pragma unroll
        for (int j = 0; j < 4; j++) {
            float x0 = c[j] + bl[j], x1 = c[4 + j] + bh[j];
            if (GELU) { x0 = gelu_t(x0); x1 = gelu_t(x1); }
            c[j] = x0; c[4 + j] = x1;
        }
        float* Cp = C + (size_t)(row0 + i) * N + col0;
        *(float4*)(Cp) = make_float4(c[0], c[1], c[2], c[3]);
        *(float4*)(Cp + 32) = make_float4(c[4], c[5], c[6], c[7]);
    }
}

__global__ __launch_bounds__(256)
void dec2_table(const float* __restrict__ X, const float* __restrict__ W,
                const float* __restrict__ b, float* __restrict__ outT) {
    __shared__ float xs[8][512];
    const int tid = threadIdx.x;
    const size_t rb = (size_t)blockIdx.x * 8;
    for (int e = tid; e < 8 * 512; e += 256) xs[e >> 9][e & 511] = X[rb * 512 + e];
    __syncthreads();
    const int r = tid >> 5, j = tid & 31;
    float a0 = 0.f, a1 = 0.f, a2 = 0.f, a3 = 0.f;
#pragma unroll 4
    for (int k = 0; k < 512; k += 4) {
        a0 = fmaf(xs[r][k + 0], W[(k + 0) * 32 + j], a0);
        a1 = fmaf(xs[r][k + 1], W[(k + 1) * 32 + j], a1);
        a2 = fmaf(xs[r][k + 2], W[(k + 2) * 32 + j], a2);
        a3 = fmaf(xs[r][k + 3], W[(k + 3) * 32 + j], a3);
    }
    outT[(rb + r) * 32 + j] = (a0 + a1) + (a2 + a3) + b[j];
}

// codebook: normalize + squared norms
__global__ void prep_cb(const float* __restrict__ cb) {
    int warp = (blockIdx.x * blockDim.x + threadIdx.x) >> 5;
    int lane = threadIdx.x & 31;
    if (warp >= 1024) return;
    const float* x = cb + (size_t)warp * 256;
    float v[8]; float s = 0.f;
#pragma unroll
    for (int i = 0; i < 8; i++) { v[i] = x[lane + i * 32]; s += v[i] * v[i]; }
#pragma unroll
    for (int o = 16; o; o >>= 1) s += __shfl_xor_sync(0xffffffffu, s, o);
    float den = sqrtf(s) + 1e-8f;
    float s2 = 0.f;
#pragma unroll
    for (int i = 0; i < 8; i++) {
        float y = v[i] / den;
        g_cbn[(size_t)warp * 256 + lane + i * 32] = y;
        s2 += y * y;
    }
#pragma unroll
    for (int o = 16; o; o >>= 1) s2 += __shfl_xor_sync(0xffffffffu, s2, o);
    if (lane == 0) g_cbsq[warp] = s2;
}

// weight transpose: W[K,N] -> Wt[N,K]
__global__ void wtrans(const float* __restrict__ W, float* __restrict__ Wt, int K, int N) {
    int i = blockIdx.x * 256 + threadIdx.x;
    if (i >= K * N) return;
    int k = i / N, n = i % N;
    Wt[(size_t)n * K + k] = W[i];
}

__global__ void zero_acc() { g_acc[0] = 0.0; g_acc[1] = 0.0; }

__global__ void finalize_losses(float* __restrict__ lossOut) {
    lossOut[0] = (float)(g_acc[0] / (65536.0 * 32.0));
    float vq = (float)(g_acc[1] / (65536.0 * 256.0));
    lossOut[1] = vq; lossOut[2] = vq;
}

extern "C" void kernel_launch(void* const* d_in, const int* in_sizes, int n_in,
                              void* d_out, int out_size) {
    const float* action = (const float*)d_in[0];
    const float* dimw = (const float*)d_in[1];
    const float* ew0 = (const float*)d_in[2];
    const float* eb0 = (const float*)d_in[3];
    const float* ew1 = (const float*)d_in[4];
    const float* eb1 = (const float*)d_in[5];
    const float* ew2 = (const float*)d_in[6];
    const float* eb2 = (const float*)d_in[7];
    const float* dw0 = (const float*)d_in[8];
    const float* db0 = (const float*)d_in[9];
    const float* dw1 = (const float*)d_in[10];
    const float* db1 = (const float*)d_in[11];
    const float* dw2 = (const float*)d_in[12];
    const float* db2 = (const float*)d_in[13];
    const float* cb = (const float*)d_in[14];
    float* out = (float*)d_out;

    void *pA, *pB, *pZE, *pW1, *pW2, *pCBN, *pD0, *pD1, *pD2;
    cudaGetSymbolAddress(&pA, g_bufA);
    cudaGetSymbolAddress(&pB, g_bufB);
    cudaGetSymbolAddress(&pZE, g_ze);
    cudaGetSymbolAddress(&pW1, g_w1t);
    cudaGetSymbolAddress(&pW2, g_w2t);
    cudaGetSymbolAddress(&pCBN, g_cbn);
    cudaGetSymbolAddress(&pD0, g_dt0);
    cudaGetSymbolAddress(&pD1, g_dt1);
    cudaGetSymbolAddress(&pD2, g_dt2);

    const size_t OFF_IDX = (size_t)NTOK * ADIM;
    const size_t OFF_LOSS = OFF_IDX + NTOK;
    const int SMEM = 4 * 128 * KP * 4;   // 73728 B

    cudaFuncSetAttribute(tmma<true>, cudaFuncAttributeMaxDynamicSharedMemorySize, SMEM);
    cudaFuncSetAttribute(tmma<false>, cudaFuncAttributeMaxDynamicSharedMemorySize, SMEM);
    cudaFuncSetAttribute(vq_t, cudaFuncAttributeMaxDynamicSharedMemorySize, SMEM);

    // ncu empirically captures launch #4 -> tmma e1 there
    sgemm_e0<<<dim3(4, 512), 256>>>(action, ew0, eb0, (float*)pA, NTOK, 512, 32);           // 1
    wtrans<<<(512 * 1024 + 255) / 256, 256>>>(ew1, (float*)pW1, 512, 1024);                 // 2
    zero_acc<<<1, 1>>>();                                                                    // 3
    tmma<true><<<dim3(8, 512), 256, SMEM>>>((float*)pA, (float*)pW1, eb1,
                                            (float*)pB, 1024, 512);                          // 4 <- profiled
    wtrans<<<(1024 * 256 + 255) / 256, 256>>>(ew2, (float*)pW2, 1024, 256);
    prep_cb<<<128, 256>>>(cb);
    sgemm64<true><<<dim3(16, 16), 128>>>((float*)pCBN, dw0, db0, (float*)pD0, 1024, 1024, 256);
    sgemm64<true><<<dim3(8, 16), 128>>>((float*)pD0, dw1, db1, (float*)pD1, 1024, 512, 1024);
    dec2_table<<<128, 256>>>((float*)pD1, dw2, db2, (float*)pD2);
    tmma<false><<<dim3(2, 512), 256, SMEM>>>((float*)pB, (float*)pW2, eb2, (float*)pZE, 256, 1024);
    vq_t<<<512, 256, SMEM>>>((float*)pZE, (float*)pD2, action, dimw, out, out + OFF_IDX);
    finalize_losses<<<1, 1>>>(out + OFF_LOSS);
}

// round 16
// speedup vs baseline: 1.0037x; 1.0037x over previous
#include <cuda_runtime.h>
#include <math.h>
#include <stdint.h>

#define NTOK 65536
#define ADIM 32
typedef unsigned long long ull;

__device__ float g_bufA[(size_t)NTOK * 512];
__device__ float g_bufB[(size_t)NTOK * 1024];
__device__ float g_ze [(size_t)NTOK * 256];
__device__ float g_w1h[1024 * 512];
__device__ float g_w1l[1024 * 512];
__device__ float g_w2h[256 * 1024];
__device__ float g_w2l[256 * 1024];
__device__ float g_cbn[1024 * 256];
__device__ float g_cbsq[1024];
__device__ float g_dt0[1024 * 1024];
__device__ float g_dt1[1024 * 512];
__device__ float g_dt2[1024 * 32];
__device__ double g_acc[2];

// ---- helpers ----
__device__ __forceinline__ ull f2pack(float lo, float hi) {
    ull r; asm("mov.b64 %0, {%1, %2};" : "=l"(r) : "f"(lo), "f"(hi)); return r;
}
__device__ __forceinline__ void f2unpack(ull p, float& lo, float& hi) {
    asm("mov.b64 {%0, %1}, %2;" : "=f"(lo), "=f"(hi) : "l"(p));
}
__device__ __forceinline__ void fma2(ull& d, ull a, ull b) {
    asm("fma.rn.f32x2 %0, %1, %2, %0;" : "+l"(d) : "l"(a), "l"(b));
}
__device__ __forceinline__ float tf32_rn(float x) {
    unsigned u; asm("cvt.rna.tf32.f32 %0, %1;" : "=r"(u) : "f"(x));
    return __uint_as_float(u);
}
__device__ __forceinline__ float gelu_t(float x) {
    float u = 0.7978845608028654f * (x + 0.044715f * x * x * x);
    return 0.5f * x * (1.0f + tanhf(u));
}
__device__ __forceinline__ void mma8(float* c, const uint32_t* a, const uint32_t* b) {
    asm volatile(
        "mma.sync.aligned.m16n8k8.row.col.f32.tf32.tf32.f32 "
        "{%0,%1,%2,%3}, {%4,%5,%6,%7}, {%8,%9}, {%0,%1,%2,%3};"
        : "+f"(c[0]), "+f"(c[1]), "+f"(c[2]), "+f"(c[3])
        : "r"(a[0]), "r"(a[1]), "r"(a[2]), "r"(a[3]), "r"(b[0]), "r"(b[1]));
}
__device__ __forceinline__ void ldm4(uint32_t* d, uint32_t a) {
    asm volatile("ldmatrix.sync.aligned.m8n8.x4.shared.b16 {%0,%1,%2,%3}, [%4];"
        : "=r"(d[0]), "=r"(d[1]), "=r"(d[2]), "=r"(d[3]) : "r"(a));
}
__device__ __forceinline__ uint32_t smem_addr(const void* p) {
    uint32_t a;
    asm("{ .reg .u64 t; cvta.to.shared.u64 t, %1; cvt.u32.u64 %0, t; }" : "=r"(a) : "l"(p));
    return a;
}
__device__ __forceinline__ void cpa16(uint32_t s, const void* g) {
    asm volatile("cp.async.cg.shared.global [%0], [%1], 16;" :: "r"(s), "l"(g));
}
__device__ __forceinline__ void cpa_commit() {
    asm volatile("cp.async.commit_group;" ::: "memory");
}
__device__ __forceinline__ void cpa_wait1() {
    asm volatile("cp.async.wait_group 1;" ::: "memory");
}
__device__ __forceinline__ void cpa_wait0() {
    asm volatile("cp.async.wait_group 0;" ::: "memory");
}
__device__ __forceinline__ void split4(float4 v, float4& h, float4& l) {
    h.x = tf32_rn(v.x); l.x = tf32_rn(v.x - h.x);
    h.y = tf32_rn(v.y); l.y = tf32_rn(v.y - h.y);
    h.z = tf32_rn(v.z); l.z = tf32_rn(v.z - h.z);
    h.w = tf32_rn(v.w); l.w = tf32_rn(v.w - h.w);
}

#define KP 36        // padded smem pitch (floats); ldmatrix row-starts conflict-free
#define ASZ (128 * KP)   // 4608 floats per operand array

// 4 k8-steps of 3-split mma over one 32-wide K tile (warp tile 64x32), ldmatrix loads
__device__ __forceinline__ void mma_ktile(const float (*Ah)[KP], const float (*Al)[KP],
                                          const float (*Bh)[KP], const float (*Bl)[KP],
                                          int wm, int wn, int lane, float acc[4][4][4]) {
    const int j8 = lane & 7;
    const int arow = wm * 64 + ((lane >> 3) & 1) * 8 + j8;
    const int acol = (lane >> 4) << 2;
    const int brow = wn * 32 + ((lane >> 4) << 3) + j8;
    const int bcol = ((lane >> 3) & 1) << 2;
    const uint32_t aAh = smem_addr(&Ah[arow][acol]);
    const uint32_t aAl = smem_addr(&Al[arow][acol]);
    const uint32_t aBh = smem_addr(&Bh[brow][bcol]);
    const uint32_t aBl = smem_addr(&Bl[brow][bcol]);
    const uint32_t MT = 16 * KP * 4;
#pragma unroll
    for (int ks = 0; ks < 4; ks++) {
        const uint32_t ko = ks * 32;
        uint32_t ah[4][4], bh[2][4], bl[2][4];
#pragma unroll
        for (int mt = 0; mt < 4; mt++) ldm4(ah[mt], aAh + mt * MT + ko);
#pragma unroll
        for (int p = 0; p < 2; p++) {
            ldm4(bh[p], aBh + p * MT + ko);
            ldm4(bl[p], aBl + p * MT + ko);
        }
#pragma unroll
        for (int mt = 0; mt < 4; mt++)
#pragma unroll
            for (int nt = 0; nt < 4; nt++) {
                mma8(acc[mt][nt], ah[mt], &bh[nt >> 1][(nt & 1) * 2]);
                mma8(acc[mt][nt], ah[mt], &bl[nt >> 1][(nt & 1) * 2]);
            }
        uint32_t al_[4][4];
#pragma unroll
        for (int mt = 0; mt < 4; mt++) ldm4(al_[mt], aAl + mt * MT + ko);
#pragma unroll
        for (int mt = 0; mt < 4; mt++)
#pragma unroll
            for (int nt = 0; nt < 4; nt++)
                mma8(acc[mt][nt], al_[mt], &bh[nt >> 1][(nt & 1) * 2]);
    }
}

// ---- tensor-op 3-split TF32 GEMM: C = act(A[M,K] @ B[N,K]^T + bias) ----
// A fp32, register-prefetched, split at STS. B pre-split (hi/lo in gmem),
// streamed via cp.async into a double-buffered smem region (zero register cost).
template<bool GELU>
__global__ __launch_bounds__(256, 2)
void tmma(const float* __restrict__ A, const float* __restrict__ Bh_,
          const float* __restrict__ Bl_, const float* __restrict__ bias,
          float* __restrict__ C, int N, int K) {
    extern __shared__ float sm[];
    float (*Ah)[KP] = (float(*)[KP])sm;
    float (*Al)[KP] = (float(*)[KP])(sm + ASZ);
    const int tid = threadIdx.x, wid = tid >> 5, lane = tid & 31;
    const int g = lane >> 2, t = lane & 3;
    const int wm = wid & 1, wn = wid >> 1;
    const size_t m0 = (size_t)blockIdx.y * 128;
    const int n0 = blockIdx.x * 128;
    const int r_ = tid >> 3, c4_ = (tid & 7) << 2;   // rows r_+32i, fixed col group
    const uint32_t sb = smem_addr(sm);
    const uint32_t dstOff = (uint32_t)(r_ * KP + c4_) * 4;

    float acc[4][4][4] = {};
    float4 pa[4];
    const int T = K >> 5;
#pragma unroll
    for (int i = 0; i < 4; i++)
        pa[i] = *(const float4*)(A + (m0 + r_ + 32 * i) * (size_t)K + c4_);
    // preamble: cp.async B tile 0 into buffer 0
    {
        const uint32_t bh0 = sb + 2 * ASZ * 4;
#pragma unroll
        for (int i = 0; i < 4; i++) {
            size_t gb = ((size_t)n0 + r_ + 32 * i) * (size_t)K + c4_;
            uint32_t off = dstOff + (uint32_t)(32 * i * KP) * 4;
            cpa16(bh0 + off,           Bh_ + gb);
            cpa16(bh0 + ASZ * 4 + off, Bl_ + gb);
        }
        cpa_commit();
    }

    for (int kt = 0; kt < T; kt++) {
        __syncthreads();   // all warps done with prev mma: A smem + buf[(kt+1)&1] free
        if (kt + 1 < T) {
            const int kn = (kt + 1) << 5;
            const uint32_t bhN = sb + (2 + 2 * ((kt + 1) & 1)) * ASZ * 4;
#pragma unroll
            for (int i = 0; i < 4; i++) {
                size_t gb = ((size_t)n0 + r_ + 32 * i) * (size_t)K + kn + c4_;
                uint32_t off = dstOff + (uint32_t)(32 * i * KP) * 4;
                cpa16(bhN + off,           Bh_ + gb);
                cpa16(bhN + ASZ * 4 + off, Bl_ + gb);
            }
            cpa_commit();
        }
#pragma unroll
        for (int i = 0; i < 4; i++) {
            float4 h, l;
            split4(pa[i], h, l);
            *(float4*)&Ah[r_ + 32 * i][c4_] = h; *(float4*)&Al[r_ + 32 * i][c4_] = l;
        }
        if (kt + 1 < T) cpa_wait1(); else cpa_wait0();
        __syncthreads();
        if (kt + 1 < T) {
            const int kn = (kt + 1) << 5;
#pragma unroll
            for (int i = 0; i < 4; i++)
                pa[i] = *(const float4*)(A + (m0 + r_ + 32 * i) * (size_t)K + kn + c4_);
        }
        const float (*Bh)[KP] = (const float(*)[KP])(sm + (2 + 2 * (kt & 1)) * ASZ);
        const float (*Bl)[KP] = (const float(*)[KP])(sm + (3 + 2 * (kt & 1)) * ASZ);
        mma_ktile(Ah, Al, Bh, Bl, wm, wn, lane, acc);
    }

#pragma unroll
    for (int mt = 0; mt < 4; mt++) {
#pragma unroll
        for (int nt = 0; nt < 4; nt++) {
            int col = n0 + wn * 32 + nt * 8 + 2 * t;
            float b0 = bias[col], b1 = bias[col + 1];
            size_t r0 = (m0 + wm * 64 + mt * 16 + g) * (size_t)N + col;
            size_t r1 = r0 + 8 * (size_t)N;
            float x0 = acc[mt][nt][0] + b0, x1 = acc[mt][nt][1] + b1;
            float x2 = acc[mt][nt][2] + b0, x3 = acc[mt][nt][3] + b1;
            if (GELU) { x0 = gelu_t(x0); x1 = gelu_t(x1); x2 = gelu_t(x2); x3 = gelu_t(x3); }
            *(float2*)(C + r0) = make_float2(x0, x1);
            *(float2*)(C + r1) = make_float2(x2, x3);
        }
    }
}

// ---- tensor-op VQ (R14 version): dist GEMM + argmin + losses + gather ----
__global__ __launch_bounds__(256, 2)
void vq_t(const float* __restrict__ ZE, const float* __restrict__ tab,
          const float* __restrict__ action, const float* __restrict__ dimw,
          float* __restrict__ outAH, float* __restrict__ outIdxF) {
    extern __shared__ float sm[];
    float (*Ah)[KP] = (float(*)[KP])sm;
    float (*Al)[KP] = (float(*)[KP])(sm + ASZ);
    float (*Bh)[KP] = (float(*)[KP])(sm + 2 * ASZ);
    float (*Bl)[KP] = (float(*)[KP])(sm + 3 * ASZ);
    __shared__ float scb[1024];
    __shared__ ull bestp[128];
    __shared__ float salpha[128], snorm[128], sdimw[32];
    __shared__ double dred[8], rred[8];
    const int tid = threadIdx.x, wid = tid >> 5, lane = tid & 31;
    const int g = lane >> 2, t = lane & 3;
    const int wm = wid & 1, wn = wid >> 1;
    const size_t m0 = (size_t)blockIdx.x * 128;
    const int r_ = tid >> 3, c4_ = (tid & 7) << 2;

    for (int e = tid; e < 1024; e += 256) scb[e] = g_cbsq[e];
    if (tid < 32) sdimw[tid] = dimw[tid];
    if (tid < 128) bestp[tid] = ~0ull;
    {
        const int row = tid >> 1, half = tid & 1;
        const float* rp = ZE + (m0 + row) * 256 + half * 128;
        float s = 0.f;
#pragma unroll
        for (int i = 0; i < 32; i++) {
            float4 v = *(const float4*)(rp + i * 4);
            s += v.x * v.x + v.y * v.y + v.z * v.z + v.w * v.w;
        }
        s += __shfl_xor_sync(0xffffffffu, s, 1);
        if (half == 0) { snorm[row] = s; salpha[row] = 1.0f / (sqrtf(s) + 1e-8f); }
    }
    __syncthreads();

    for (int ct = 0; ct < 8; ct++) {
        const int cbase = ct * 128;
        float acc[4][4][4] = {};
        for (int kt = 0; kt < 8; kt++) {
            const int kg = kt << 5;
            __syncthreads();
#pragma unroll
            for (int i = 0; i < 4; i++) {
                float4 va = *(const float4*)(ZE + (m0 + r_ + 32 * i) * 256 + kg + c4_);
                float4 h, l;
                split4(va, h, l);
                *(float4*)&Ah[r_ + 32 * i][c4_] = h; *(float4*)&Al[r_ + 32 * i][c4_] = l;
                float4 vb = *(const float4*)(g_cbn + ((size_t)cbase + r_ + 32 * i) * 256 + kg + c4_);
                split4(vb, h, l);
                *(float4*)&Bh[r_ + 32 * i][c4_] = h; *(float4*)&Bl[r_ + 32 * i][c4_] = l;
            }
            __syncthreads();
            mma_ktile(Ah, Al, Bh, Bl, wm, wn, lane, acc);
        }
#pragma unroll
        for (int mt = 0; mt < 4; mt++) {
            const int r0 = wm * 64 + mt * 16 + g, r1 = r0 + 8;
            const float m2a0 = -2.0f * salpha[r0], m2a1 = -2.0f * salpha[r1];
            ull p0 = ~0ull, p1 = ~0ull;
#pragma unroll
            for (int nt = 0; nt < 4; nt++) {
                int c = cbase + wn * 32 + nt * 8 + 2 * t;
                float s0 = scb[c], s1 = scb[c + 1];
                float v00 = fmaf(m2a0, acc[mt][nt][0], s0);
                float v01 = fmaf(m2a0, acc[mt][nt][1], s1);
                float v10 = fmaf(m2a1, acc[mt][nt][2], s0);
                float v11 = fmaf(m2a1, acc[mt][nt][3], s1);
                p0 = min(p0, ((ull)__float_as_uint(v00 + 8.f) << 32) | (unsigned)c);
                p0 = min(p0, ((ull)__float_as_uint(v01 + 8.f) << 32) | (unsigned)(c + 1));
                p1 = min(p1, ((ull)__float_as_uint(v10 + 8.f) << 32) | (unsigned)c);
                p1 = min(p1, ((ull)__float_as_uint(v11 + 8.f) << 32) | (unsigned)(c + 1));
            }
#pragma unroll
            for (int off = 1; off < 4; off <<= 1) {
                p0 = min(p0, __shfl_xor_sync(0xffffffffu, p0, off));
                p1 = min(p1, __shfl_xor_sync(0xffffffffu, p1, off));
            }
            if (t == 0) { atomicMin(&bestp[r0], p0); atomicMin(&bestp[r1], p1); }
        }
        __syncthreads();
    }

    double lsum = 0.0;
    if (tid < 128) {
        ull bp = bestp[tid];
        int besti = (int)(unsigned)(bp & 0xffffffffu);
        outIdxF[blockIdx.x * 128 + tid] = (float)besti;
        float bd = __uint_as_float((unsigned)(bp >> 32)) - 8.0f;
        float a = salpha[tid];
        lsum = (double)(a * a * snorm[tid] + bd);
    }
#pragma unroll
    for (int o = 16; o; o >>= 1) lsum += __shfl_xor_sync(0xffffffffu, lsum, o);
    if ((tid & 31) == 0) dred[tid >> 5] = lsum;

    double rsum = 0.0;
    for (int rr = wid; rr < 128; rr += 8) {
        int idx = (int)(unsigned)(bestp[rr] & 0xffffffffu);
        float ah = tab[(size_t)idx * 32 + lane];
        size_t gi = (m0 + rr) * 32 + lane;
        outAH[gi] = ah;
        float d = action[gi] - ah;
        rsum += (double)(d * d * sdimw[lane]);
    }
#pragma unroll
    for (int o = 16; o; o >>= 1) rsum += __shfl_xor_sync(0xffffffffu, rsum, o);
    if (lane == 0) rred[wid] = rsum;
    __syncthreads();
    if (tid == 0) {
        double tt = 0.0, r = 0.0;
        for (int i = 0; i < 8; i++) { tt += dred[i]; r += rred[i]; }
        atomicAdd(&g_acc[1], tt);
        atomicAdd(&g_acc[0], r);
    }
}

// ---- fp32 FFMA GEMM for e0 ----
#define SPAD 132
__global__ __launch_bounds__(256, 2)
void sgemm_e0(const float* __restrict__ A, const float* __restrict__ B,
              const float* __restrict__ bias, float* __restrict__ C, int M, int N, int K) {
    __shared__ float As[2][16][SPAD];
    __shared__ float Bs[2][16][SPAD];
    const int tid = threadIdx.x;
    const int tx = tid & 15, ty = tid >> 4;
    const int aRow = tid >> 2, aCol4 = (tid & 3) << 2;
    const int bRow = tid >> 5, bCol4 = (tid & 31) << 2;
    const float* Ab = A + (size_t)blockIdx.y * 128 * K;
    const float* Bb = B + (size_t)blockIdx.x * 128;
    ull acc[8][4];
#pragma unroll
    for (int i = 0; i < 8; i++)
#pragma unroll
        for (int j = 0; j < 4; j++) acc[i][j] = 0ull;
    const int T = K >> 4;
    float4 pa0, pa1, pb0, pb1;
    pa0 = *(const float4*)(Ab + (size_t)aRow * K + aCol4);
    pa1 = *(const float4*)(Ab + (size_t)(aRow + 64) * K + aCol4);
    pb0 = *(const float4*)(Bb + (size_t)bRow * N + bCol4);
    pb1 = *(const float4*)(Bb + (size_t)(bRow + 8) * N + bCol4);
    {
        float* a0p = &As[0][aCol4][aRow];
        a0p[0] = pa0.x; a0p[SPAD] = pa0.y; a0p[2 * SPAD] = pa0.z; a0p[3 * SPAD] = pa0.w;
        float* a1p = &As[0][aCol4][aRow + 64];
        a1p[0] = pa1.x; a1p[SPAD] = pa1.y; a1p[2 * SPAD] = pa1.z; a1p[3 * SPAD] = pa1.w;
        *(float4*)(&Bs[0][bRow][bCol4]) = pb0;
        *(float4*)(&Bs[0][bRow + 8][bCol4]) = pb1;
    }
    __syncthreads();
    for (int tt = 0; tt < T; tt++) {
        const int cur = tt & 1;
        if (tt + 1 < T) {
            const int k0 = (tt + 1) << 4;
            pa0 = *(const float4*)(Ab + (size_t)aRow * K + k0 + aCol4);
            pa1 = *(const float4*)(Ab + (size_t)(aRow + 64) * K + k0 + aCol4);
            pb0 = *(const float4*)(Bb + (size_t)(k0 + bRow) * N + bCol4);
            pb1 = *(const float4*)(Bb + (size_t)(k0 + bRow + 8) * N + bCol4);
        }
#pragma unroll
        for (int k = 0; k < 16; k++) {
            float4 a0 = *(const float4*)(&As[cur][k][ty * 4]);
            float4 a1 = *(const float4*)(&As[cur][k][ty * 4 + 64]);
            ulonglong2 b01 = *(const ulonglong2*)(&Bs[cur][k][tx * 4]);
            ulonglong2 b23 = *(const ulonglong2*)(&Bs[cur][k][tx * 4 + 64]);
            ull bb2[4] = {b01.x, b01.y, b23.x, b23.y};
            float af[8] = {a0.x, a0.y, a0.z, a0.w, a1.x, a1.y, a1.z, a1.w};
#pragma unroll
            for (int i = 0; i < 8; i++) {
                ull a2 = f2pack(af[i], af[i]);
#pragma unroll
                for (int jp = 0; jp < 4; jp++) fma2(acc[i][jp], a2, bb2[jp]);
            }
        }
        if (tt + 1 < T) {
            const int nxt = cur ^ 1;
            float* a0p = &As[nxt][aCol4][aRow];
            a0p[0] = pa0.x; a0p[SPAD] = pa0.y; a0p[2 * SPAD] = pa0.z; a0p[3 * SPAD] = pa0.w;
            float* a1p = &As[nxt][aCol4][aRow + 64];
            a1p[0] = pa1.x; a1p[SPAD] = pa1.y; a1p[2 * SPAD] = pa1.z; a1p[3 * SPAD] = pa1.w;
            *(float4*)(&Bs[nxt][bRow][bCol4]) = pb0;
            *(float4*)(&Bs[nxt][bRow + 8][bCol4]) = pb1;
        }
        __syncthreads();
    }
    const int row0 = blockIdx.y * 128;
    const int c0g = blockIdx.x * 128 + tx * 4;
    float bl[4], bh[4];
#pragma unroll
    for (int j = 0; j < 4; j++) { bl[j] = bias[c0g + j]; bh[j] = bias[c0g + 64 + j]; }
#pragma unroll
    for (int i = 0; i < 8; i++) {
        const int row = row0 + ((i < 4) ? (ty * 4 + i) : (64 + ty * 4 + i - 4));
        float c[8];
#pragma unroll
        for (int jp = 0; jp < 4; jp++) f2unpack(acc[i][jp], c[jp * 2], c[jp * 2 + 1]);
#pragma unroll
        for (int j = 0; j < 4; j++) {
            c[j] = gelu_t(c[j] + bl[j]);
            c[4 + j] = gelu_t(c[4 + j] + bh[j]);
        }
        float* Cp = C + (size_t)row * N + c0g;
        *(float4*)(Cp) = make_float4(c[0], c[1], c[2], c[3]);
        *(float4*)(Cp + 64) = make_float4(c[4], c[5], c[6], c[7]);
    }
}

// ---- small fp32 GEMM for decoder table ----
template<bool GELU>
__global__ __launch_bounds__(128)
void sgemm64(const float* __restrict__ A, const float* __restrict__ B,
             const float* __restrict__ bias, float* __restrict__ C, int M, int N, int K) {
    __shared__ float As[16][68];
    __shared__ float Bs[16][68];
    const int tid = threadIdx.x;
    const int tx = tid & 7, ty = tid >> 3;
    const int aRow = tid >> 1, aCol8 = (tid & 1) * 8;
    const int bRow = tid >> 3, bCol8 = (tid & 7) * 8;
    const float* Ab = A + (size_t)blockIdx.y * 64 * K;
    const float* Bb = B + (size_t)blockIdx.x * 64;
    ull acc[4][4];
#pragma unroll
    for (int i = 0; i < 4; i++)
#pragma unroll
        for (int j = 0; j < 4; j++) acc[i][j] = 0ull;
    for (int k0 = 0; k0 < K; k0 += 16) {
        float4 va0 = *(const float4*)(Ab + (size_t)aRow * K + k0 + aCol8);
        float4 va1 = *(const float4*)(Ab + (size_t)aRow * K + k0 + aCol8 + 4);
        float4 vb0 = *(const float4*)(Bb + (size_t)(k0 + bRow) * N + bCol8);
        float4 vb1 = *(const float4*)(Bb + (size_t)(k0 + bRow) * N + bCol8 + 4);
        __syncthreads();
        As[aCol8 + 0][aRow] = va0.x; As[aCol8 + 1][aRow] = va0.y;
        As[aCol8 + 2][aRow] = va0.z; As[aCol8 + 3][aRow] = va0.w;
        As[aCol8 + 4][aRow] = va1.x; As[aCol8 + 5][aRow] = va1.y;
        As[aCol8 + 6][aRow] = va1.z; As[aCol8 + 7][aRow] = va1.w;
        *(float4*)(&Bs[bRow][bCol8]) = vb0;
        *(float4*)(&Bs[bRow][bCol8 + 4]) = vb1;
        __syncthreads();
#pragma unroll
        for (int k = 0; k < 16; k++) {
            float4 a = *(const float4*)(&As[k][ty * 4]);
            ulonglong2 b01 = *(const ulonglong2*)(&Bs[k][tx * 4]);
            ulonglong2 b23 = *(const ulonglong2*)(&Bs[k][tx * 4 + 32]);
            ull bb2[4] = {b01.x, b01.y, b23.x, b23.y};
            float af[4] = {a.x, a.y, a.z, a.w};
#pragma unroll
            for (int i = 0; i < 4; i++) {
                ull a2 = f2pack(af[i], af[i]);
#pragma unroll
                for (int jp = 0; jp < 4; jp++) fma2(acc[i][jp], a2, bb2[jp]);
            }
        }
    }
    const int row0 = blockIdx.y * 64 + ty * 4;
    const int col0 = blockIdx.x * 64 + tx * 4;
    float bl[4], bh[4];
#pragma unroll
    for (int j = 0; j < 4; j++) { bl[j] = bias[col0 + j]; bh[j] = bias[col0 + 32 + j]; }
#pragma unroll
    for (int i = 0; i < 4; i++) {
        float c[8];
#pragma unroll
        for (int jp = 0; jp < 4; jp++) f2unpack(acc[i][jp], c[jp * 2], c[jp * 2 + 1]);
#pragma unroll
        for (int j = 0; j < 4; j++) {
            float x0 = c[j] + bl[j], x1 = c[4 + j] + bh[j];
            if (GELU) { x0 = gelu_t(x0); x1 = gelu_t(x1); }
            c[j] = x0; c[4 + j] = x1;
        }
        float* Cp = C + (size_t)(row0 + i) * N + col0;
        *(float4*)(Cp) = make_float4(c[0], c[1], c[2], c[3]);
        *(float4*)(Cp + 32) = make_float4(c[4], c[5], c[6], c[7]);
    }
}

__global__ __launch_bounds__(256)
void dec2_table(const float* __restrict__ X, const float* __restrict__ W,
                const float* __restrict__ b, float* __restrict__ outT) {
    __shared__ float xs[8][512];
    const int tid = threadIdx.x;
    const size_t rb = (size_t)blockIdx.x * 8;
    for (int e = tid; e < 8 * 512; e += 256) xs[e >> 9][e & 511] = X[rb * 512 + e];
    __syncthreads();
    const int r = tid >> 5, j = tid & 31;
    float a0 = 0.f, a1 = 0.f, a2 = 0.f, a3 = 0.f;
#pragma unroll 4
    for (int k = 0; k < 512; k += 4) {
        a0 = fmaf(xs[r][k + 0], W[(k + 0) * 32 + j], a0);
        a1 = fmaf(xs[r][k + 1], W[(k + 1) * 32 + j], a1);
        a2 = fmaf(xs[r][k + 2], W[(k + 2) * 32 + j], a2);
        a3 = fmaf(xs[r][k + 3], W[(k + 3) * 32 + j], a3);
    }
    outT[(rb + r) * 32 + j] = (a0 + a1) + (a2 + a3) + b[j];
}

// codebook: normalize + squared norms
__global__ void prep_cb(const float* __restrict__ cb) {
    int warp = (blockIdx.x * blockDim.x + threadIdx.x) >> 5;
    int lane = threadIdx.x & 31;
    if (warp >= 1024) return;
    const float* x = cb + (size_t)warp * 256;
    float v[8]; float s = 0.f;
#pragma unroll
    for (int i = 0; i < 8; i++) { v[i] = x[lane + i * 32]; s += v[i] * v[i]; }
#pragma unroll
    for (int o = 16; o; o >>= 1) s += __shfl_xor_sync(0xffffffffu, s, o);
    float den = sqrtf(s) + 1e-8f;
    float s2 = 0.f;
#pragma unroll
    for (int i = 0; i < 8; i++) {
        float y = v[i] / den;
        g_cbn[(size_t)warp * 256 + lane + i * 32] = y;
        s2 += y * y;
    }
#pragma unroll
    for (int o = 16; o; o >>= 1) s2 += __shfl_xor_sync(0xffffffffu, s2, o);
    if (lane == 0) g_cbsq[warp] = s2;
}

// weight transpose + tf32 split: W[K,N] -> oh/ol [N,K]
__global__ void wsplit(const float* __restrict__ W, float* __restrict__ oh,
                       float* __restrict__ ol, int K, int N) {
    int i = blockIdx.x * 256 + threadIdx.x;
    if (i >= K * N) return;
    int k = i / N, n = i % N;
    float x = W[i];
    float h = tf32_rn(x);
    oh[(size_t)n * K + k] = h;
    ol[(size_t)n * K + k] = tf32_rn(x - h);
}

__global__ void zero_acc() { g_acc[0] = 0.0; g_acc[1] = 0.0; }

__global__ void finalize_losses(float* __restrict__ lossOut) {
    lossOut[0] = (float)(g_acc[0] / (65536.0 * 32.0));
    float vq = (float)(g_acc[1] / (65536.0 * 256.0));
    lossOut[1] = vq; lossOut[2] = vq;
}

extern "C" void kernel_launch(void* const* d_in, const int* in_sizes, int n_in,
                              void* d_out, int out_size) {
    const float* action = (const float*)d_in[0];
    const float* dimw = (const float*)d_in[1];
    const float* ew0 = (const float*)d_in[2];
    const float* eb0 = (const float*)d_in[3];
    const float* ew1 = (const float*)d_in[4];
    const float* eb1 = (const float*)d_in[5];
    const float* ew2 = (const float*)d_in[6];
    const float* eb2 = (const float*)d_in[7];
    const float* dw0 = (const float*)d_in[8];
    const float* db0 = (const float*)d_in[9];
    const float* dw1 = (const float*)d_in[10];
    const float* db1 = (const float*)d_in[11];
    const float* dw2 = (const float*)d_in[12];
    const float* db2 = (const float*)d_in[13];
    const float* cb = (const float*)d_in[14];
    float* out = (float*)d_out;

    void *pA, *pB, *pZE, *pw1h, *pw1l, *pw2h, *pw2l, *pCBN, *pD0, *pD1, *pD2;
    cudaGetSymbolAddress(&pA, g_bufA);
    cudaGetSymbolAddress(&pB, g_bufB);
    cudaGetSymbolAddress(&pZE, g_ze);
    cudaGetSymbolAddress(&pw1h, g_w1h); cudaGetSymbolAddress(&pw1l, g_w1l);
    cudaGetSymbolAddress(&pw2h, g_w2h); cudaGetSymbolAddress(&pw2l, g_w2l);
    cudaGetSymbolAddress(&pCBN, g_cbn);
    cudaGetSymbolAddress(&pD0, g_dt0);
    cudaGetSymbolAddress(&pD1, g_dt1);
    cudaGetSymbolAddress(&pD2, g_dt2);

    const size_t OFF_IDX = (size_t)NTOK * ADIM;
    const size_t OFF_LOSS = OFF_IDX + NTOK;
    const int SMEM_T = 6 * ASZ * 4;   // 110592 B: A(h,l) + double-buffered B(h,l)
    const int SMEM_V = 4 * ASZ * 4;   // 73728 B: vq single-buffered

    cudaFuncSetAttribute(tmma<true>, cudaFuncAttributeMaxDynamicSharedMemorySize, SMEM_T);
    cudaFuncSetAttribute(tmma<false>, cudaFuncAttributeMaxDynamicSharedMemorySize, SMEM_T);
    cudaFuncSetAttribute(vq_t, cudaFuncAttributeMaxDynamicSharedMemorySize, SMEM_V);

    // ncu empirically captures launch #4 -> tmma e1 there
    sgemm_e0<<<dim3(4, 512), 256>>>(action, ew0, eb0, (float*)pA, NTOK, 512, 32);              // 1
    wsplit<<<(512 * 1024 + 255) / 256, 256>>>(ew1, (float*)pw1h, (float*)pw1l, 512, 1024);     // 2
    zero_acc<<<1, 1>>>();                                                                       // 3
    tmma<true><<<dim3(8, 512), 256, SMEM_T>>>((float*)pA, (float*)pw1h, (float*)pw1l, eb1,
                                              (float*)pB, 1024, 512);                           // 4 <- profiled
    wsplit<<<(1024 * 256 + 255) / 256, 256>>>(ew2, (float*)pw2h, (float*)pw2l, 1024, 256);
    prep_cb<<<128, 256>>>(cb);
    sgemm64<true><<<dim3(16, 16), 128>>>((float*)pCBN, dw0, db0, (float*)pD0, 1024, 1024, 256);
    sgemm64<true><<<dim3(8, 16), 128>>>((float*)pD0, dw1, db1, (float*)pD1, 1024, 512, 1024);
    dec2_table<<<128, 256>>>((float*)pD1, dw2, db2, (float*)pD2);
    tmma<false><<<dim3(2, 512), 256, SMEM_T>>>((float*)pB, (float*)pw2h, (float*)pw2l, eb2,
                                               (float*)pZE, 256, 1024);
    vq_t<<<512, 256, SMEM_V>>>((float*)pZE, (float*)pD2, action, dimw, out, out + OFF_IDX);
    finalize_losses<<<1, 1>>>(out + OFF_LOSS);
}